// round 16
// baseline (speedup 1.0000x reference)
#include <cuda_runtime.h>
#include <cstdint>

// Problem constants
#define B_   4
#define H_   384
#define W_   1280
#define GH_  192                 // int(0.5 * 384)
#define N_   (GH_ * W_)          // 245760 ground points per batch
#define HW_  (H_ * W_)           // 491520
#define HYP  25                  // MAX_IT
#define NPTS 5
#define TOLF 0.1f

// k_fit: grid (80, 4) x 256 threads, 3 float4/thread -> 80*256*3 = N_/4 exact
#define GA_X  80
#define TA    256
#define FPT_A 3
// k_dist: grid (240, 4) x 128 threads, TMA tile of 2048 floats (8 KB)
#define GB_X  240
#define TB    128
#define TF    2048               // floats per tile; 240*2048 = HW_ exact
#define TBYTES (TF * 4)          // 8192

// Scratch (no cudaMalloc; zero-initialized; k_fit's ticket resets g_cnt/g_done
// every run so graph replays are deterministic)
__device__ int          g_cnt[B_ * HYP];
__device__ unsigned int g_done[B_];
__device__ float        g_best[B_ * 3];

// ---------------------------------------------------------------------------
// Packed f32x2 helpers (sm_103a). Per-lane rn rounding identical to scalar
// FFMA/FADD, so inlier counts are bit-identical to the scalar formulation.
// ---------------------------------------------------------------------------
__device__ __forceinline__ void fma2(float& d0, float& d1,
                                     float a0, float a1,
                                     float b0, float b1,
                                     float c0, float c1) {
    asm("{\n\t.reg .b64 A,B,C,D;\n\t"
        "mov.b64 A,{%2,%3};\n\t"
        "mov.b64 B,{%4,%5};\n\t"
        "mov.b64 C,{%6,%7};\n\t"
        "fma.rn.f32x2 D,A,B,C;\n\t"
        "mov.b64 {%0,%1},D;\n\t}"
        : "=f"(d0), "=f"(d1)
        : "f"(a0), "f"(a1), "f"(b0), "f"(b1), "f"(c0), "f"(c1));
}
__device__ __forceinline__ void add2(float& d0, float& d1,
                                     float a0, float a1,
                                     float b0, float b1) {
    asm("{\n\t.reg .b64 A,B,D;\n\t"
        "mov.b64 A,{%2,%3};\n\t"
        "mov.b64 B,{%4,%5};\n\t"
        "add.rn.f32x2 D,A,B;\n\t"
        "mov.b64 {%0,%1},D;\n\t}"
        : "=f"(d0), "=f"(d1)
        : "f"(a0), "f"(a1), "f"(b0), "f"(b1));
}

// ---------------------------------------------------------------------------
// Async-copy helpers (sm_90+ 1D bulk copies; no tensormap needed)
// ---------------------------------------------------------------------------
__device__ __forceinline__ uint32_t smem_u32(const void* p) {
    uint32_t a;
    asm("{ .reg .u64 t; cvta.to.shared.u64 t, %1; cvt.u32.u64 %0, t; }"
        : "=r"(a) : "l"(p));
    return a;
}
__device__ __forceinline__ void bulk_ld(uint32_t dst_smem, const void* src,
                                        uint32_t bytes, uint32_t bar) {
    asm volatile(
        "cp.async.bulk.shared::cta.global.mbarrier::complete_tx::bytes "
        "[%0], [%1], %2, [%3];"
        :: "r"(dst_smem), "l"(src), "r"(bytes), "r"(bar) : "memory");
}
__device__ __forceinline__ void bulk_st(void* dst, uint32_t src_smem,
                                        uint32_t bytes) {
    asm volatile(
        "cp.async.bulk.global.shared::cta.bulk_group [%0], [%1], %2;"
        :: "l"(dst), "r"(src_smem), "r"(bytes) : "memory");
}
__device__ __forceinline__ void mbar_init(uint32_t bar, uint32_t cnt) {
    asm volatile("mbarrier.init.shared.b64 [%0], %1;" :: "r"(bar), "r"(cnt)
                 : "memory");
}
__device__ __forceinline__ void mbar_expect_tx(uint32_t bar, uint32_t bytes) {
    asm volatile("mbarrier.arrive.expect_tx.shared.b64 _, [%0], %1;"
                 :: "r"(bar), "r"(bytes) : "memory");
}
__device__ __forceinline__ void mbar_wait(uint32_t bar, uint32_t parity) {
    uint32_t done;
    do {
        asm volatile(
            "{\n\t.reg .pred p;\n\t"
            "mbarrier.try_wait.parity.acquire.cta.shared::cta.b64 p, [%1], %2, 0x989680;\n\t"
            "selp.b32 %0, 1, 0, p;\n\t}"
            : "=r"(done) : "r"(bar), "r"(parity) : "memory");
    } while (!done);
}

// ---------------------------------------------------------------------------
// Kernel A (unchanged from best R15): fused solve + count + argmax.
// M = A^T A + 1e-6 on EVERY entry (matches jnp broadcast).
// ---------------------------------------------------------------------------
__global__ void __launch_bounds__(TA) k_fit(const float* __restrict__ pts,
                                            const int* __restrict__ rind,
                                            float* __restrict__ out_bw) {
    const int b   = blockIdx.y;
    const int tid = threadIdx.x;

    const float* gb = pts + (size_t)b * 3 * HW_ + (size_t)(H_ - GH_) * W_;
    const float4* xs = (const float4*)gb;
    const float4* ys = xs + (HW_ / 4);
    const float4* zs = xs + 2 * (HW_ / 4);

    // 1) sample index load first (hides under bulk loads)
    int n = -1;
    if (tid < HYP * NPTS) n = __ldg(rind + b * (HYP * NPTS) + tid);

    // 2) bulk loads: 9 independent LDG.128 per thread
    const int v0 = blockIdx.x * (TA * FPT_A) + tid;
    float4 X[FPT_A], nY[FPT_A], Z[FPT_A];
#pragma unroll
    for (int i = 0; i < FPT_A; i++) {
        X[i] = xs[v0 + i * TA];
        Z[i] = zs[v0 + i * TA];
        float4 y = ys[v0 + i * TA];
        nY[i] = make_float4(-y.x, -y.y, -y.z, -y.w);
    }

    __shared__ float sx[HYP * NPTS], sy[HYP * NPTS], sz[HYP * NPTS];
    __shared__ float s_w[HYP * 3];
    __shared__ int   s_c[HYP];

    // 3) dependent sample gathers (rind already in flight)
    if (tid < HYP * NPTS) {
        sx[tid] = __ldg(gb + n);
        sy[tid] = __ldg(gb + HW_ + n);
        sz[tid] = __ldg(gb + 2 * HW_ + n);
    }
    if (tid < HYP) s_c[tid] = 0;
    __syncthreads();

    // 4) solve (threads 0..24, one hypothesis each, fp64, short chain)
    if (tid < HYP) {
        int o = tid * NPTS;
        double x0 = sx[o], x1 = sx[o+1], x2 = sx[o+2], x3 = sx[o+3], x4 = sx[o+4];
        double y0 = sy[o], y1 = sy[o+1], y2 = sy[o+2], y3 = sy[o+3], y4 = sy[o+4];
        double z0 = sz[o], z1 = sz[o+1], z2 = sz[o+2], z3 = sz[o+3], z4 = sz[o+4];

        #define PW(e0,e1,e2,e3,e4) (((e0)+(e1)) + (((e2)+(e3)) + (e4)))
        double Sxx = PW(x0*x0, x1*x1, x2*x2, x3*x3, x4*x4);
        double Sxz = PW(x0*z0, x1*z1, x2*z2, x3*z3, x4*z4);
        double Sx  = PW(x0, x1, x2, x3, x4);
        double Szz = PW(z0*z0, z1*z1, z2*z2, z3*z3, z4*z4);
        double Sz  = PW(z0, z1, z2, z3, z4);
        double Sxy = PW(x0*y0, x1*y1, x2*y2, x3*y3, x4*y4);
        double Szy = PW(z0*y0, z1*y1, z2*y2, z3*y3, z4*y4);
        double Sy  = PW(y0, y1, y2, y3, y4);
        #undef PW

        const double e = 1e-6;
        double a  = Sxx + e, bb = Sxz + e, c = Sx + e;
        double d  = Szz + e, f  = Sz  + e;
        double g  = (double)NPTS + e;

        double A00 = d * g - f * f;
        double A01 = c * f - bb * g;
        double A02 = bb * f - c * d;
        double A11 = a * g - c * c;
        double A12 = bb * c - a * f;
        double A22 = a * d - bb * bb;
        double det = (a * A00 + bb * A01) + c * A02;

        // fp32-seeded Newton reciprocal (~2^-46 rel err; outputs are fp32)
        double inv = (double)__frcp_rn((float)det);
        inv = inv * (2.0 - det * inv);
        inv = inv * (2.0 - det * inv);

        double r0 = Sxy, r1 = Szy, r2 = Sy;
        s_w[tid * 3 + 0] = (float)(((A00 * r0 + A01 * r1) + A02 * r2) * inv);
        s_w[tid * 3 + 1] = (float)(((A01 * r0 + A11 * r1) + A12 * r2) * inv);
        s_w[tid * 3 + 2] = (float)(((A02 * r0 + A12 * r1) + A22 * r2) * inv);
    }
    __syncthreads();

    // 5) count: packed f32x2, 12 points x 25 hypotheses per thread
    for (int k = 0; k < HYP; k++) {
        float w0 = s_w[3 * k], w1 = s_w[3 * k + 1], w2 = s_w[3 * k + 2];
        int c = 0;
#pragma unroll
        for (int i = 0; i < FPT_A; i++) {
            float t0, t1, u0, u1;
            fma2(t0, t1, Z[i].x, Z[i].y, w1, w1, w2, w2);
            fma2(u0, u1, Z[i].z, Z[i].w, w1, w1, w2, w2);
            fma2(t0, t1, X[i].x, X[i].y, w0, w0, t0, t1);
            fma2(u0, u1, X[i].z, X[i].w, w0, w0, u0, u1);
            add2(t0, t1, t0, t1, nY[i].x, nY[i].y);
            add2(u0, u1, u0, u1, nY[i].z, nY[i].w);
            c += (fabsf(t0) < TOLF);
            c += (fabsf(t1) < TOLF);
            c += (fabsf(u0) < TOLF);
            c += (fabsf(u1) < TOLF);
        }
        unsigned s = __reduce_add_sync(0xffffffffu, (unsigned)c);
        if ((tid & 31) == 0) atomicAdd(&s_c[k], (int)s);
    }
    __syncthreads();
    if (tid < HYP) atomicAdd(&g_cnt[b * HYP + tid], s_c[tid]);
    __syncthreads();

    // 6) ticket: last block per batch -> argmax + reset (deterministic replays)
    if (tid == 0) {
        __threadfence();
        unsigned old = atomicAdd(&g_done[b], 1u);
        if (old == GA_X - 1) {
            __threadfence();
            int best = 0, bc = __ldcg(&g_cnt[b * HYP]);
#pragma unroll
            for (int it = 1; it < HYP; it++) {
                int v = __ldcg(&g_cnt[b * HYP + it]);
                if (v > bc) { bc = v; best = it; }   // first-max = jnp.argmax
            }
            float bw0 = s_w[best * 3 + 0];
            float bw1 = s_w[best * 3 + 1];
            float bw2 = s_w[best * 3 + 2];
            g_best[b * 3 + 0] = bw0;
            g_best[b * 3 + 1] = bw1;
            g_best[b * 3 + 2] = bw2;
            out_bw[b * 3 + 0] = bw0;
            out_bw[b * 3 + 1] = bw1;
            out_bw[b * 3 + 2] = bw2;
            // reset for next graph replay
#pragma unroll
            for (int it = 0; it < HYP; it++) g_cnt[b * HYP + it] = 0;
            g_done[b] = 0;
            __threadfence();
        }
    }
}

// ---------------------------------------------------------------------------
// Kernel B: signed distance via 1D bulk-async copies.
// Each block: one 2048-float tile. cp.async.bulk x/y/z tiles into smem
// (one mbarrier, expect_tx 24 KB) -> compute from smem -> cp.async.bulk
// result tile smem->global (bulk_group, wait_group 0 before exit).
// Data movement is decoupled from warp scoreboards: ~960 block-level copies
// in flight chip-wide.
// ---------------------------------------------------------------------------
__global__ void __launch_bounds__(TB) k_dist(const float* __restrict__ pts,
                                             float* __restrict__ out) {
    const int b   = blockIdx.y;
    const int tid = threadIdx.x;

    __shared__ alignas(16) unsigned long long s_bar;
    __shared__ alignas(16) float s_x[TF];
    __shared__ alignas(16) float s_y[TF];
    __shared__ alignas(16) float s_z[TF];
    __shared__ alignas(16) float s_o[TF];

    const float* base = pts + (size_t)b * 3 * HW_ + (size_t)blockIdx.x * TF;
    float* gout = out + (size_t)b * HW_ + (size_t)blockIdx.x * TF;

    const uint32_t bar = smem_u32(&s_bar);

    if (tid == 0) mbar_init(bar, 1);
    __syncthreads();

    if (tid == 0) {
        mbar_expect_tx(bar, 3 * TBYTES);
        bulk_ld(smem_u32(s_x), base,            TBYTES, bar);
        bulk_ld(smem_u32(s_y), base + HW_,      TBYTES, bar);
        bulk_ld(smem_u32(s_z), base + 2 * HW_,  TBYTES, bar);
    }

    // g_best visible via stream order (k_fit completed before this kernel)
    const float w0 = g_best[b * 3 + 0];
    const float w1 = g_best[b * 3 + 1];
    const float w2 = g_best[b * 3 + 2];

    mbar_wait(bar, 0);

    const float4* sX = (const float4*)s_x;
    const float4* sY = (const float4*)s_y;
    const float4* sZ = (const float4*)s_z;
    float4*       sO = (float4*)s_o;

#pragma unroll
    for (int k = 0; k < TF / 4 / TB; k++) {       // 4 float4 per thread
        int i = tid + k * TB;
        float4 X = sX[i], Y = sY[i], Z = sZ[i];
        float4 r;
        r.x = fmaf(X.x, w0, fmaf(Z.x, w1, w2)) - Y.x;
        r.y = fmaf(X.y, w0, fmaf(Z.y, w1, w2)) - Y.y;
        r.z = fmaf(X.z, w0, fmaf(Z.z, w1, w2)) - Y.z;
        r.w = fmaf(X.w, w0, fmaf(Z.w, w1, w2)) - Y.w;
        sO[i] = r;
    }

    __syncthreads();
    if (tid == 0) {
        asm volatile("fence.proxy.async.shared::cta;" ::: "memory");
        bulk_st(gout, smem_u32(s_o), TBYTES);
        asm volatile("cp.async.bulk.commit_group;" ::: "memory");
        asm volatile("cp.async.bulk.wait_group 0;" ::: "memory");
    }
}

// ---------------------------------------------------------------------------
// Launch: 2 kernels, plain stream order, graph-capturable (no syncs/allocs).
// Output layout: dist (B*H*W floats) followed by best_w (B*3 floats).
// ---------------------------------------------------------------------------
extern "C" void kernel_launch(void* const* d_in, const int* in_sizes, int n_in,
                              void* d_out, int out_size) {
    const float* pts  = (const float*)d_in[0];
    const int*   rind = (const int*)d_in[1];
    float*       out  = (float*)d_out;

    k_fit<<<dim3(GA_X, B_), TA>>>(pts, rind, out + (size_t)B_ * HW_);
    k_dist<<<dim3(GB_X, B_), TB>>>(pts, out);
}

// round 17
// speedup vs baseline: 1.0577x; 1.0577x over previous
#include <cuda_runtime.h>
#include <cstdint>

// Problem constants
#define B_   4
#define H_   384
#define W_   1280
#define GH_  192                 // int(0.5 * 384)
#define N_   (GH_ * W_)          // 245760 ground points per batch
#define HW_  (H_ * W_)           // 491520
#define HYP  25                  // MAX_IT
#define NPTS 5
#define TOLF 0.1f

// Geometry: per batch 120 tiles of 1024 float4 (256 thr x 4 f4).
// 1D grid of 480 blocks, GROUND TILES FIRST (bids 0..239) so producers are
// always in wave 1 -> the best-flag spin is deadlock-free at any occupancy.
#define TILES 120                // tiles per batch
#define GT    60                 // ground tiles per batch (tiles 60..119)
#define FPT   4                  // float4 per thread
#define NBLK  (B_ * TILES)       // 480

// Scratch (no cudaMalloc; zero-initialized; self-resetting each run)
__device__ int          g_cnt[B_ * HYP];
__device__ unsigned int g_done[B_];
__device__ unsigned int g_bestflag[B_];
__device__ unsigned int g_ack[B_];
__device__ float        g_best[B_ * 3];

// ---------------------------------------------------------------------------
// Packed f32x2 helpers (sm_103a). Per-lane rn rounding identical to scalar
// FFMA/FADD, so inlier counts are bit-identical to the scalar formulation.
// ---------------------------------------------------------------------------
__device__ __forceinline__ void fma2(float& d0, float& d1,
                                     float a0, float a1,
                                     float b0, float b1,
                                     float c0, float c1) {
    asm("{\n\t.reg .b64 A,B,C,D;\n\t"
        "mov.b64 A,{%2,%3};\n\t"
        "mov.b64 B,{%4,%5};\n\t"
        "mov.b64 C,{%6,%7};\n\t"
        "fma.rn.f32x2 D,A,B,C;\n\t"
        "mov.b64 {%0,%1},D;\n\t}"
        : "=f"(d0), "=f"(d1)
        : "f"(a0), "f"(a1), "f"(b0), "f"(b1), "f"(c0), "f"(c1));
}
__device__ __forceinline__ void add2(float& d0, float& d1,
                                     float a0, float a1,
                                     float b0, float b1) {
    asm("{\n\t.reg .b64 A,B,D;\n\t"
        "mov.b64 A,{%2,%3};\n\t"
        "mov.b64 B,{%4,%5};\n\t"
        "add.rn.f32x2 D,A,B;\n\t"
        "mov.b64 {%0,%1},D;\n\t}"
        : "=f"(d0), "=f"(d1)
        : "f"(a0), "f"(a1), "f"(b0), "f"(b1));
}

// ---------------------------------------------------------------------------
// ONE kernel: load once -> (ground blocks) solve + count + ticket argmax ->
// (all blocks) wait best -> dist from resident registers -> store.
// M = A^T A + 1e-6 on EVERY entry (matches jnp broadcast).
// First-max tie rule on argmax (= jnp.argmax).
// ---------------------------------------------------------------------------
__global__ void __launch_bounds__(256, 3) k_all(const float* __restrict__ pts,
                                                const int* __restrict__ rind,
                                                float* __restrict__ out,
                                                float* __restrict__ out_bw) {
    const int bid = blockIdx.x;
    const int tid = threadIdx.x;

    // Ground-first decode: bids 0..239 -> tiles 60..119; 240..479 -> 0..59.
    const bool ground = (bid < B_ * GT);
    const int  b  = ground ? (bid / GT) : ((bid - B_ * GT) / GT);
    const int  gx = ground ? (GT + bid % GT) : ((bid - B_ * GT) % GT);

    const float*  base = pts + (size_t)b * 3 * HW_;
    const float4* xs = (const float4*)base;
    const float4* ys = xs + (HW_ / 4);
    const float4* zs = xs + 2 * (HW_ / 4);
    float4* o = (float4*)(out + (size_t)b * HW_);

    // Sample index load first for ground blocks (hides under bulk loads)
    int n = -1;
    if (ground && tid < HYP * NPTS) n = __ldg(rind + b * (HYP * NPTS) + tid);

    // Bulk loads: 12 independent LDG.128 per thread; data stays resident for
    // both count and dist. y stored negated for the f32x2 count form.
    const int v0 = gx * (256 * FPT) + tid;
    float4 X[FPT], nY[FPT], Z[FPT];
#pragma unroll
    for (int i = 0; i < FPT; i++) {
        X[i] = xs[v0 + i * 256];
        Z[i] = zs[v0 + i * 256];
        float4 y = ys[v0 + i * 256];
        nY[i] = make_float4(-y.x, -y.y, -y.z, -y.w);
    }

    __shared__ float sx[HYP * NPTS], sy[HYP * NPTS], sz[HYP * NPTS];
    __shared__ float s_w[HYP * 3];
    __shared__ int   s_c[HYP];

    if (ground) {
        const float* gb = base + (size_t)(H_ - GH_) * W_;
        // Gather the batch's 125 samples (L2-hot after the first blocks)
        if (tid < HYP * NPTS) {
            sx[tid] = __ldg(gb + n);
            sy[tid] = __ldg(gb + HW_ + n);
            sz[tid] = __ldg(gb + 2 * HW_ + n);
        }
        if (tid < HYP) s_c[tid] = 0;
        __syncthreads();

        // Solve (threads 0..24, one hypothesis each, fp64, short chain)
        if (tid < HYP) {
            int oo = tid * NPTS;
            double x0 = sx[oo], x1 = sx[oo+1], x2 = sx[oo+2], x3 = sx[oo+3], x4 = sx[oo+4];
            double y0 = sy[oo], y1 = sy[oo+1], y2 = sy[oo+2], y3 = sy[oo+3], y4 = sy[oo+4];
            double z0 = sz[oo], z1 = sz[oo+1], z2 = sz[oo+2], z3 = sz[oo+3], z4 = sz[oo+4];

            #define PW(e0,e1,e2,e3,e4) (((e0)+(e1)) + (((e2)+(e3)) + (e4)))
            double Sxx = PW(x0*x0, x1*x1, x2*x2, x3*x3, x4*x4);
            double Sxz = PW(x0*z0, x1*z1, x2*z2, x3*z3, x4*z4);
            double Sx  = PW(x0, x1, x2, x3, x4);
            double Szz = PW(z0*z0, z1*z1, z2*z2, z3*z3, z4*z4);
            double Sz  = PW(z0, z1, z2, z3, z4);
            double Sxy = PW(x0*y0, x1*y1, x2*y2, x3*y3, x4*y4);
            double Szy = PW(z0*y0, z1*y1, z2*y2, z3*y3, z4*y4);
            double Sy  = PW(y0, y1, y2, y3, y4);
            #undef PW

            const double e = 1e-6;
            double a  = Sxx + e, bb = Sxz + e, c = Sx + e;
            double d  = Szz + e, f  = Sz  + e;
            double g  = (double)NPTS + e;

            double A00 = d * g - f * f;
            double A01 = c * f - bb * g;
            double A02 = bb * f - c * d;
            double A11 = a * g - c * c;
            double A12 = bb * c - a * f;
            double A22 = a * d - bb * bb;
            double det = (a * A00 + bb * A01) + c * A02;

            // fp32-seeded Newton reciprocal (~2^-46 rel err; outputs fp32)
            double inv = (double)__frcp_rn((float)det);
            inv = inv * (2.0 - det * inv);
            inv = inv * (2.0 - det * inv);

            double r0 = Sxy, r1 = Szy, r2 = Sy;
            s_w[tid * 3 + 0] = (float)(((A00 * r0 + A01 * r1) + A02 * r2) * inv);
            s_w[tid * 3 + 1] = (float)(((A01 * r0 + A11 * r1) + A12 * r2) * inv);
            s_w[tid * 3 + 2] = (float)(((A02 * r0 + A12 * r1) + A22 * r2) * inv);
        }
        __syncthreads();

        // Count: packed f32x2, 16 points x 25 hypotheses per thread, all data
        // in registers (no per-hyp LDS traffic)
        for (int k = 0; k < HYP; k++) {
            float w0 = s_w[3 * k], w1 = s_w[3 * k + 1], w2 = s_w[3 * k + 2];
            int c = 0;
#pragma unroll
            for (int i = 0; i < FPT; i++) {
                float t0, t1, u0, u1;
                fma2(t0, t1, Z[i].x, Z[i].y, w1, w1, w2, w2);
                fma2(u0, u1, Z[i].z, Z[i].w, w1, w1, w2, w2);
                fma2(t0, t1, X[i].x, X[i].y, w0, w0, t0, t1);
                fma2(u0, u1, X[i].z, X[i].w, w0, w0, u0, u1);
                add2(t0, t1, t0, t1, nY[i].x, nY[i].y);
                add2(u0, u1, u0, u1, nY[i].z, nY[i].w);
                c += (fabsf(t0) < TOLF);
                c += (fabsf(t1) < TOLF);
                c += (fabsf(u0) < TOLF);
                c += (fabsf(u1) < TOLF);
            }
            unsigned s = __reduce_add_sync(0xffffffffu, (unsigned)c);
            if ((tid & 31) == 0) atomicAdd(&s_c[k], (int)s);
        }
        __syncthreads();
        if (tid < HYP) atomicAdd(&g_cnt[b * HYP + tid], s_c[tid]);
        __syncthreads();

        // Ticket: last ground block of this batch -> argmax + reset + flag
        if (tid == 0) {
            __threadfence();
            unsigned old = atomicAdd(&g_done[b], 1u);
            if (old == GT - 1) {
                __threadfence();
                int best = 0, bc = __ldcg(&g_cnt[b * HYP]);
#pragma unroll
                for (int it = 1; it < HYP; it++) {
                    int v = __ldcg(&g_cnt[b * HYP + it]);
                    if (v > bc) { bc = v; best = it; }
                }
                float bw0 = s_w[best * 3 + 0];
                float bw1 = s_w[best * 3 + 1];
                float bw2 = s_w[best * 3 + 2];
                g_best[b * 3 + 0] = bw0;
                g_best[b * 3 + 1] = bw1;
                g_best[b * 3 + 2] = bw2;
                out_bw[b * 3 + 0] = bw0;
                out_bw[b * 3 + 1] = bw1;
                out_bw[b * 3 + 2] = bw2;
                // reset count state (only argmax reads g_cnt) for next replay
#pragma unroll
                for (int it = 0; it < HYP; it++) g_cnt[b * HYP + it] = 0;
                g_done[b] = 0;
                __threadfence();
                atomicExch(&g_bestflag[b], 1u);   // release
            }
        }
    }

    // All blocks: wait for this batch's best plane (producers are bids
    // 0..239, always scheduled in wave 1 -> progress guaranteed)
    if (tid == 0) {
        while (__ldcg((const unsigned int*)&g_bestflag[b]) == 0u) __nanosleep(64);
        __threadfence();                          // acquire
    }
    __syncthreads();

    const float w0 = __ldcg(&g_best[b * 3 + 0]);
    const float w1 = __ldcg(&g_best[b * 3 + 1]);
    const float w2 = __ldcg(&g_best[b * 3 + 2]);

    // Dist from resident registers (reference-exact form; nY holds -y)
#pragma unroll
    for (int i = 0; i < FPT; i++) {
        float4 r;
        r.x = fmaf(X[i].x, w0, fmaf(Z[i].x, w1, w2)) + nY[i].x;
        r.y = fmaf(X[i].y, w0, fmaf(Z[i].y, w1, w2)) + nY[i].y;
        r.z = fmaf(X[i].z, w0, fmaf(Z[i].z, w1, w2)) + nY[i].z;
        r.w = fmaf(X[i].w, w0, fmaf(Z[i].w, w1, w2)) + nY[i].w;
        o[v0 + i * 256] = r;
    }

    // Ack ticket: last block of this batch resets the flag for next replay
    __syncthreads();
    if (tid == 0) {
        unsigned a = atomicAdd(&g_ack[b], 1u);
        if (a == TILES - 1) {
            g_ack[b] = 0;
            __threadfence();
            atomicExch(&g_bestflag[b], 0u);
        }
    }
}

// ---------------------------------------------------------------------------
// Launch: ONE kernel, graph-capturable (no syncs, no allocs).
// Output layout: dist (B*H*W floats) followed by best_w (B*3 floats).
// ---------------------------------------------------------------------------
extern "C" void kernel_launch(void* const* d_in, const int* in_sizes, int n_in,
                              void* d_out, int out_size) {
    const float* pts  = (const float*)d_in[0];
    const int*   rind = (const int*)d_in[1];
    float*       out  = (float*)d_out;

    k_all<<<NBLK, 256>>>(pts, rind, out, out + (size_t)B_ * HW_);
}